// round 15
// baseline (speedup 1.0000x reference)
#include <cuda_runtime.h>
#include <cuda_bf16.h>
#include <math.h>
#include <stdint.h>

#define NTOK 8192
#define DIM  1024
#define INV_SCALE 0.08838834764831843f   // 1/sqrt(128)

// ---------------------------------------------------------------------------
// Scratch (device globals; no allocation allowed)
// ---------------------------------------------------------------------------
__device__ __nv_bfloat16 g_xb[(size_t)NTOK * DIM];
__device__ __nv_bfloat16 g_wob[(size_t)DIM * DIM];
__device__ __nv_bfloat16 g_wqT[(size_t)DIM * DIM];
__device__ __nv_bfloat16 g_wkT[(size_t)DIM * DIM];
__device__ __nv_bfloat16 g_wvT[(size_t)DIM * DIM];
__device__ __nv_bfloat16 g_Mt[(size_t)DIM * DIM];    // (Wq^T Wk)^T
__device__ __nv_bfloat16 g_W2[(size_t)DIM * DIM];    // Wo*Wv
__device__ __nv_bfloat16 g_y[(size_t)NTOK * DIM];    // x*M + wv (bf16)
__device__ __nv_bfloat16 g_PT[(size_t)DIM * NTOK];   // (v*Wo^T)^T
__device__ __nv_bfloat16 g_att[(size_t)NTOK * NTOK]; // exp(z'*inv_scale)
__device__ float g_wv[DIM];                          // Wk^T * bq
__device__ float g_bv2[DIM];                         // Wo * bv

// ---------------------------------------------------------------------------
// Helpers
// ---------------------------------------------------------------------------
__device__ __forceinline__ uint32_t smem_u32(const void* p) {
    uint32_t a;
    asm("{ .reg .u64 t; cvta.to.shared.u64 t, %1; cvt.u32.u64 %0, t; }" : "=r"(a) : "l"(p));
    return a;
}
__device__ __forceinline__ uint32_t swz(uint32_t x) { return x ^ ((x >> 3) & 0x70); }

__device__ __forceinline__ void cp16(uint32_t saddr, const void* g) {
    asm volatile("cp.async.cg.shared.global [%0], [%1], 16;\n" :: "r"(saddr), "l"(g));
}
__device__ __forceinline__ void cp_commit() { asm volatile("cp.async.commit_group;\n" ::); }
template <int N> __device__ __forceinline__ void cp_wait() {
    asm volatile("cp.async.wait_group %0;\n" :: "n"(N));
}

__device__ __forceinline__ void ldsm_x4(uint32_t addr, uint32_t* r) {
    asm volatile("ldmatrix.sync.aligned.m8n8.x4.shared.b16 {%0,%1,%2,%3}, [%4];"
        : "=r"(r[0]), "=r"(r[1]), "=r"(r[2]), "=r"(r[3]) : "r"(addr));
}

__device__ __forceinline__ void mma_bf16(float* c, const uint32_t* a, const uint32_t* b) {
    asm volatile("mma.sync.aligned.m16n8k16.row.col.f32.bf16.bf16.f32 "
        "{%0,%1,%2,%3}, {%4,%5,%6,%7}, {%8,%9}, {%0,%1,%2,%3};"
        : "+f"(c[0]), "+f"(c[1]), "+f"(c[2]), "+f"(c[3])
        : "r"(a[0]), "r"(a[1]), "r"(a[2]), "r"(a[3]), "r"(b[0]), "r"(b[1]));
}

__device__ __forceinline__ uint32_t pack_bf16(float lo, float hi) {
    uint32_t r;
    asm("cvt.rn.bf16x2.f32 %0, %1, %2;" : "=r"(r) : "f"(hi), "f"(lo));
    return r;
}

#define BM 128
#define BN 128
#define BK 64
#define T_ST_BYTES (128 * 128)
#define SMEM_B_OFF (3 * T_ST_BYTES)
#define SMEM_TOTAL (6 * T_ST_BYTES)              // 98304

// ---------------------------------------------------------------------------
// 256-thread body: 8 warps (2M x 4N), warp tile 64x32, 2 CTAs/SM.
// bf16 output with optional col bias and/or row bias.
// ---------------------------------------------------------------------------
__device__ __forceinline__ void gemm_body_b16(
    const __nv_bfloat16* __restrict__ A,
    const __nv_bfloat16* __restrict__ B,
    const float* __restrict__ cbias,
    const float* __restrict__ rbias,
    __nv_bfloat16* __restrict__ C,
    int Nn, int K, int bm, int bn, char* smem)
{
    const uint32_t sb = smem_u32(smem);
    const int tid = threadIdx.x, lane = tid & 31, wid = tid >> 5;
    const int wn = wid & 3, wm = wid >> 2;

    float acc[4][4][4];
    #pragma unroll
    for (int i = 0; i < 4; i++)
        #pragma unroll
        for (int j = 0; j < 4; j++)
            #pragma unroll
            for (int q = 0; q < 4; q++) acc[i][j][q] = 0.0f;

    const int KT = K / BK;

    auto load_stage = [&](int s, int kt) {
        const int k0 = kt * BK;
        const uint32_t ab = sb + s * T_ST_BYTES;
        const __nv_bfloat16* Ag = A + (size_t)bm * K + k0;
        #pragma unroll
        for (int i = 0; i < 4; i++) {
            int c = tid + (i << 8);
            int r = c >> 3, kc = c & 7;
            cp16(ab + swz((r << 7) + (kc << 4)), Ag + (size_t)r * K + (kc << 3));
        }
        const uint32_t bb = sb + SMEM_B_OFF + s * T_ST_BYTES;
        const __nv_bfloat16* Bg = B + (size_t)bn * K + k0;
        #pragma unroll
        for (int i = 0; i < 4; i++) {
            int c = tid + (i << 8);
            int r = c >> 3, kc = c & 7;
            cp16(bb + swz((r << 7) + (kc << 4)), Bg + (size_t)r * K + (kc << 3));
        }
        cp_commit();
    };

    load_stage(0, 0);
    load_stage(1, 1);

    const int g = lane >> 3, r8 = lane & 7;
    const int a_row = wm * 64 + (g & 1) * 8 + r8;
    const int a_kb  = (g >> 1) * 16;
    const int b_row = wn * 32 + (g >> 1) * 8 + r8;
    const int b_kb  = (g & 1) * 16;

    int s = 0;
    for (int kt = 0; kt < KT; kt++) {
        if (kt + 1 < KT) cp_wait<1>(); else cp_wait<0>();
        __syncthreads();

        if (kt + 2 < KT) load_stage((kt + 2) % 3, kt + 2);

        const uint32_t abase = sb + s * T_ST_BYTES;
        const uint32_t bbase = sb + SMEM_B_OFF + s * T_ST_BYTES;

        #pragma unroll
        for (int ks = 0; ks < 4; ks++) {
            uint32_t a[4][4], b[2][4];
            #pragma unroll
            for (int mt = 0; mt < 4; mt++)
                ldsm_x4(abase + swz(((a_row + mt * 16) << 7) + ks * 32 + a_kb), a[mt]);
            #pragma unroll
            for (int np = 0; np < 2; np++)
                ldsm_x4(bbase + swz(((b_row + np * 16) << 7) + ks * 32 + b_kb), b[np]);
            #pragma unroll
            for (int mt = 0; mt < 4; mt++)
                #pragma unroll
                for (int np = 0; np < 2; np++) {
                    mma_bf16(acc[mt][np * 2],     a[mt], &b[np][0]);
                    mma_bf16(acc[mt][np * 2 + 1], a[mt], &b[np][2]);
                }
        }
        s++; if (s == 3) s = 0;
    }

    const int lr = lane >> 2, lc = (lane & 3) * 2;

    #pragma unroll
    for (int mt = 0; mt < 4; mt++) {
        #pragma unroll
        for (int h = 0; h < 2; h++) {
            const int row = bm + wm * 64 + mt * 16 + h * 8 + lr;
            const float rb = rbias ? rbias[row] : 0.0f;
            #pragma unroll
            for (int nt = 0; nt < 4; nt++) {
                const int col = bn + wn * 32 + nt * 8 + lc;
                float v0 = acc[mt][nt][h * 2]     + rb;
                float v1 = acc[mt][nt][h * 2 + 1] + rb;
                if (cbias) { v0 += cbias[col]; v1 += cbias[col + 1]; }
                uint32_t* dst = (uint32_t*)(C + (size_t)row * Nn + col);
                *dst = pack_bf16(v0, v1);
            }
        }
    }
}

// small matrix products: z=0: Mt = NT(WkT, WqT); z=1: W2 = NT(Wo, WvT)
__global__ __launch_bounds__(256, 2)
void gemm_smallmm()
{
    extern __shared__ char smem[];
    const __nv_bfloat16* A = (blockIdx.z == 0) ? g_wkT : g_wob;
    const __nv_bfloat16* B = (blockIdx.z == 0) ? g_wqT : g_wvT;
    __nv_bfloat16* C       = (blockIdx.z == 0) ? g_Mt  : g_W2;
    gemm_body_b16(A, B, nullptr, nullptr, C, DIM, DIM,
                  blockIdx.y * BM, blockIdx.x * BN, smem);
}

// projections: z=0: y = NT(xb, Mt) + wv[col]; z=1: PT = NT(W2, xb) + bv2[row]
__global__ __launch_bounds__(256, 2)
void gemm_projs()
{
    extern __shared__ char smem[];
    if (blockIdx.z == 0) {
        gemm_body_b16(g_xb, g_Mt, g_wv, nullptr, g_y, DIM, DIM,
                      blockIdx.x * BM, blockIdx.y * BN, smem);
    } else {
        gemm_body_b16(g_W2, g_xb, nullptr, g_bv2, g_PT, NTOK, DIM,
                      blockIdx.y * BM, blockIdx.x * BN, smem);
    }
}

// ---------------------------------------------------------------------------
// z GEMM: att = exp((y @ xb^T) * inv_scale)  (bf16 out)
// 128 threads, 4 warps (2M x 2N), warp tile 64x64, frag double-buffering.
// ---------------------------------------------------------------------------
__global__ __launch_bounds__(128, 2)
void gemm_z(const __nv_bfloat16* __restrict__ A,
            const __nv_bfloat16* __restrict__ B,
            __nv_bfloat16* __restrict__ att)
{
    extern __shared__ char smem[];
    const uint32_t sb = smem_u32(smem);
    const int tid = threadIdx.x, lane = tid & 31, wid = tid >> 5;
    const int wn = wid & 1, wm = wid >> 1;
    const int bm = blockIdx.y * BM, bn = blockIdx.x * BN;
    const int K = DIM, KT = K / BK;

    float acc[4][8][4];
    #pragma unroll
    for (int i = 0; i < 4; i++)
        #pragma unroll
        for (int j = 0; j < 8; j++)
            #pragma unroll
            for (int q = 0; q < 4; q++) acc[i][j][q] = 0.0f;

    auto load_stage = [&](int s, int kt) {
        const int k0 = kt * BK;
        const uint32_t ab = sb + s * T_ST_BYTES;
        const __nv_bfloat16* Ag = A + (size_t)bm * K + k0;
        #pragma unroll
        for (int i = 0; i < 8; i++) {
            int c = tid + (i << 7);
            int r = c >> 3, kc = c & 7;
            cp16(ab + swz((r << 7) + (kc << 4)), Ag + (size_t)r * K + (kc << 3));
        }
        const uint32_t bb = sb + SMEM_B_OFF + s * T_ST_BYTES;
        const __nv_bfloat16* Bg = B + (size_t)bn * K + k0;
        #pragma unroll
        for (int i = 0; i < 8; i++) {
            int c = tid + (i << 7);
            int r = c >> 3, kc = c & 7;
            cp16(bb + swz((r << 7) + (kc << 4)), Bg + (size_t)r * K + (kc << 3));
        }
        cp_commit();
    };

    load_stage(0, 0);
    load_stage(1, 1);

    const int g = lane >> 3, r8 = lane & 7;
    const int a_row = wm * 64 + (g & 1) * 8 + r8;
    const int a_kb  = (g >> 1) * 16;
    const int b_row = wn * 64 + (g >> 1) * 8 + r8;
    const int b_kb  = (g & 1) * 16;

    uint32_t a[2][4][4], b[2][4][4];

    int s = 0;
    for (int kt = 0; kt < KT; kt++) {
        if (kt + 1 < KT) cp_wait<1>(); else cp_wait<0>();
        __syncthreads();

        if (kt + 2 < KT) load_stage((kt + 2) % 3, kt + 2);

        const uint32_t abase = sb + s * T_ST_BYTES;
        const uint32_t bbase = sb + SMEM_B_OFF + s * T_ST_BYTES;

        #pragma unroll
        for (int mt = 0; mt < 4; mt++)
            ldsm_x4(abase + swz(((a_row + mt * 16) << 7) + a_kb), a[0][mt]);
        #pragma unroll
        for (int np = 0; np < 4; np++)
            ldsm_x4(bbase + swz(((b_row + np * 16) << 7) + b_kb), b[0][np]);

        #pragma unroll
        for (int ks = 0; ks < 4; ks++) {
            const int cur = ks & 1;
            if (ks < 3) {
                const int nxt = cur ^ 1;
                #pragma unroll
                for (int mt = 0; mt < 4; mt++)
                    ldsm_x4(abase + swz(((a_row + mt * 16) << 7) + (ks + 1) * 32 + a_kb), a[nxt][mt]);
                #pragma unroll
                for (int np = 0; np < 4; np++)
                    ldsm_x4(bbase + swz(((b_row + np * 16) << 7) + (ks + 1) * 32 + b_kb), b[nxt][np]);
            }
            #pragma unroll
            for (int mt = 0; mt < 4; mt++)
                #pragma unroll
                for (int np = 0; np < 4; np++) {
                    mma_bf16(acc[mt][np * 2],     a[cur][mt], &b[cur][np][0]);
                    mma_bf16(acc[mt][np * 2 + 1], a[cur][mt], &b[cur][np][2]);
                }
        }
        s++; if (s == 3) s = 0;
    }

    const int lr = lane >> 2, lc = (lane & 3) * 2;

    #pragma unroll
    for (int mt = 0; mt < 4; mt++) {
        #pragma unroll
        for (int h = 0; h < 2; h++) {
            const int row = bm + wm * 64 + mt * 16 + h * 8 + lr;
            #pragma unroll
            for (int nt = 0; nt < 8; nt++) {
                const int col = bn + wn * 64 + nt * 8 + lc;
                float v0 = __expf(acc[mt][nt][h * 2]     * INV_SCALE);
                float v1 = __expf(acc[mt][nt][h * 2 + 1] * INV_SCALE);
                uint32_t* dst = (uint32_t*)(att + (size_t)row * NTOK + col);
                *dst = pack_bf16(v0, v1);
            }
        }
    }
}

// ---------------------------------------------------------------------------
// Final GEMM with FUSED rowsum: out = (att @ PT^T)/rowsum(att) + bo + x
// 128 threads, 4 warps (2M x 2N), warp tile 64x64. Row sums accumulated from
// A fragments (regs {0,2} -> row lr, {1,3} -> row lr+8), quad shfl-reduce.
// ---------------------------------------------------------------------------
__global__ __launch_bounds__(128, 2)
void gemm_final(const __nv_bfloat16* __restrict__ A,
                const __nv_bfloat16* __restrict__ B,
                const float* __restrict__ bias,
                const float* __restrict__ res,
                float* __restrict__ out)
{
    extern __shared__ char smem[];
    const uint32_t sb = smem_u32(smem);
    const int tid = threadIdx.x, lane = tid & 31, wid = tid >> 5;
    const int wn = wid & 1, wm = wid >> 1;
    const int bm = blockIdx.y * BM, bn = blockIdx.x * BN;
    const int Nn = DIM, K = NTOK, KT = K / BK;

    float acc[4][8][4];
    #pragma unroll
    for (int i = 0; i < 4; i++)
        #pragma unroll
        for (int j = 0; j < 8; j++)
            #pragma unroll
            for (int q = 0; q < 4; q++) acc[i][j][q] = 0.0f;

    float rsum[4][2];
    #pragma unroll
    for (int i = 0; i < 4; i++) { rsum[i][0] = 0.0f; rsum[i][1] = 0.0f; }

    auto load_stage = [&](int s, int kt) {
        const int k0 = kt * BK;
        const uint32_t ab = sb + s * T_ST_BYTES;
        const __nv_bfloat16* Ag = A + (size_t)bm * K + k0;
        #pragma unroll
        for (int i = 0; i < 8; i++) {
            int c = tid + (i << 7);
            int r = c >> 3, kc = c & 7;
            cp16(ab + swz((r << 7) + (kc << 4)), Ag + (size_t)r * K + (kc << 3));
        }
        const uint32_t bb = sb + SMEM_B_OFF + s * T_ST_BYTES;
        const __nv_bfloat16* Bg = B + (size_t)bn * K + k0;
        #pragma unroll
        for (int i = 0; i < 8; i++) {
            int c = tid + (i << 7);
            int r = c >> 3, kc = c & 7;
            cp16(bb + swz((r << 7) + (kc << 4)), Bg + (size_t)r * K + (kc << 3));
        }
        cp_commit();
    };

    load_stage(0, 0);
    load_stage(1, 1);

    const int g = lane >> 3, r8 = lane & 7;
    const int a_row = wm * 64 + (g & 1) * 8 + r8;
    const int a_kb  = (g >> 1) * 16;
    const int b_row = wn * 64 + (g >> 1) * 8 + r8;
    const int b_kb  = (g & 1) * 16;

    uint32_t a[2][4][4], b[2][4][4];

    int s = 0;
    for (int kt = 0; kt < KT; kt++) {
        if (kt + 1 < KT) cp_wait<1>(); else cp_wait<0>();
        __syncthreads();

        if (kt + 2 < KT) load_stage((kt + 2) % 3, kt + 2);

        const uint32_t abase = sb + s * T_ST_BYTES;
        const uint32_t bbase = sb + SMEM_B_OFF + s * T_ST_BYTES;

        #pragma unroll
        for (int mt = 0; mt < 4; mt++)
            ldsm_x4(abase + swz(((a_row + mt * 16) << 7) + a_kb), a[0][mt]);
        #pragma unroll
        for (int np = 0; np < 4; np++)
            ldsm_x4(bbase + swz(((b_row + np * 16) << 7) + b_kb), b[0][np]);

        #pragma unroll
        for (int ks = 0; ks < 4; ks++) {
            const int cur = ks & 1;
            if (ks < 3) {
                const int nxt = cur ^ 1;
                #pragma unroll
                for (int mt = 0; mt < 4; mt++)
                    ldsm_x4(abase + swz(((a_row + mt * 16) << 7) + (ks + 1) * 32 + a_kb), a[nxt][mt]);
                #pragma unroll
                for (int np = 0; np < 4; np++)
                    ldsm_x4(bbase + swz(((b_row + np * 16) << 7) + (ks + 1) * 32 + b_kb), b[nxt][np]);
            }
            #pragma unroll
            for (int mt = 0; mt < 4; mt++) {
                #pragma unroll
                for (int np = 0; np < 4; np++) {
                    mma_bf16(acc[mt][np * 2],     a[cur][mt], &b[cur][np][0]);
                    mma_bf16(acc[mt][np * 2 + 1], a[cur][mt], &b[cur][np][2]);
                }
                // fused rowsum from A fragments
                float2 p0 = __bfloat1622float2(*reinterpret_cast<__nv_bfloat162*>(&a[cur][mt][0]));
                float2 p1 = __bfloat1622float2(*reinterpret_cast<__nv_bfloat162*>(&a[cur][mt][1]));
                float2 p2 = __bfloat1622float2(*reinterpret_cast<__nv_bfloat162*>(&a[cur][mt][2]));
                float2 p3 = __bfloat1622float2(*reinterpret_cast<__nv_bfloat162*>(&a[cur][mt][3]));
                rsum[mt][0] += (p0.x + p0.y) + (p2.x + p2.y);
                rsum[mt][1] += (p1.x + p1.y) + (p3.x + p3.y);
            }
        }
        s++; if (s == 3) s = 0;
    }

    const int lr = lane >> 2, lc = (lane & 3) * 2;

    #pragma unroll
    for (int mt = 0; mt < 4; mt++) {
        #pragma unroll
        for (int h = 0; h < 2; h++) {
            const int row = bm + wm * 64 + mt * 16 + h * 8 + lr;
            float sm = rsum[mt][h];
            sm += __shfl_xor_sync(0xFFFFFFFF, sm, 1);
            sm += __shfl_xor_sync(0xFFFFFFFF, sm, 2);
            const float rcp = 1.0f / sm;
            #pragma unroll
            for (int nt = 0; nt < 8; nt++) {
                const int col = bn + wn * 64 + nt * 8 + lc;
                const float2 rv = *(const float2*)(res + (size_t)row * Nn + col);
                float v0 = acc[mt][nt][h * 2]     * rcp + bias[col]     + rv.x;
                float v1 = acc[mt][nt][h * 2 + 1] * rcp + bias[col + 1] + rv.y;
                float2* dst = (float2*)(out + (size_t)row * Nn + col);
                *dst = make_float2(v0, v1);
            }
        }
    }
}

// ---------------------------------------------------------------------------
// small vectors: y=0: wv[e] = sum_a Wk[a,e]*bq[a]; y=1: bv2[d] = Wo[d,:].bv
// ---------------------------------------------------------------------------
__global__ __launch_bounds__(128)
void smallvec(const float* __restrict__ Wk, const float* __restrict__ bq,
              const float* __restrict__ Wo, const float* __restrict__ bv,
              float* __restrict__ wv, float* __restrict__ bv2)
{
    const int i = blockIdx.x * 128 + threadIdx.x;
    if (blockIdx.y == 0) {
        float s = 0.0f;
        #pragma unroll 8
        for (int a = 0; a < DIM; a++) s += Wk[(size_t)a * DIM + i] * bq[a];
        wv[i] = s;
    } else {
        float s = 0.0f;
        #pragma unroll 8
        for (int e = 0; e < DIM; e++) s += Wo[(size_t)i * DIM + e] * bv[e];
        bv2[i] = s;
    }
}

// converts: y=0: x -> xb (bf16), y=1: Wo -> wob
__global__ __launch_bounds__(256)
void conv2(const float* __restrict__ x, const float* __restrict__ Wo,
           __nv_bfloat16* __restrict__ xo, __nv_bfloat16* __restrict__ oo)
{
    const float* in; __nv_bfloat16* out; int n4;
    if (blockIdx.y == 0) { in = x;  out = xo; n4 = NTOK * DIM / 4; }
    else                 { in = Wo; out = oo; n4 = DIM * DIM / 4; }
    int i = blockIdx.x * blockDim.x + threadIdx.x;
    if (i >= n4) return;
    float4 v = reinterpret_cast<const float4*>(in)[i];
    uint2 o;
    o.x = pack_bf16(v.x, v.y);
    o.y = pack_bf16(v.z, v.w);
    reinterpret_cast<uint2*>(out)[i] = o;
}

// transpose-convert: out[d,f] = bf16(W[f,d]), 1024x1024, z picks Wq/Wk/Wv
__global__ __launch_bounds__(256)
void tconv(const float* __restrict__ Wq, const float* __restrict__ Wk,
           const float* __restrict__ Wv,
           __nv_bfloat16* __restrict__ oq, __nv_bfloat16* __restrict__ ok,
           __nv_bfloat16* __restrict__ ov)
{
    __shared__ float t[32][33];
    const float* in; __nv_bfloat16* out;
    if (blockIdx.z == 0)      { in = Wq; out = oq; }
    else if (blockIdx.z == 1) { in = Wk; out = ok; }
    else                      { in = Wv; out = ov; }
    const int bx = blockIdx.x * 32;
    const int by = blockIdx.y * 32;
    const int x = threadIdx.x, y = threadIdx.y;
    #pragma unroll
    for (int i = 0; i < 32; i += 8)
        t[y + i][x] = in[(size_t)(by + y + i) * DIM + bx + x];
    __syncthreads();
    #pragma unroll
    for (int i = 0; i < 32; i += 8)
        out[(size_t)(bx + y + i) * DIM + by + x] = __float2bfloat16(t[x][y + i]);
}

// ---------------------------------------------------------------------------
// Launch
// ---------------------------------------------------------------------------
extern "C" void kernel_launch(void* const* d_in, const int* in_sizes, int n_in,
                              void* d_out, int out_size)
{
    const float* x  = (const float*)d_in[0];
    const float* Wq = (const float*)d_in[1];
    const float* bq = (const float*)d_in[2];
    const float* Wk = (const float*)d_in[3];
    const float* bk = (const float*)d_in[4];
    const float* Wv = (const float*)d_in[5];
    const float* bv = (const float*)d_in[6];
    const float* Wo = (const float*)d_in[7];
    const float* bo = (const float*)d_in[8];
    float* out = (float*)d_out;
    (void)bk;  // row-constant in softmax: cancels

    __nv_bfloat16 *xb, *wob, *wqT, *wkT, *wvT, *y, *PT, *att;
    float *wv, *bv2;
    cudaGetSymbolAddress((void**)&xb,  g_xb);
    cudaGetSymbolAddress((void**)&wob, g_wob);
    cudaGetSymbolAddress((void**)&wqT, g_wqT);
    cudaGetSymbolAddress((void**)&wkT, g_wkT);
    cudaGetSymbolAddress((void**)&wvT, g_wvT);
    cudaGetSymbolAddress((void**)&y,   g_y);
    cudaGetSymbolAddress((void**)&PT,  g_PT);
    cudaGetSymbolAddress((void**)&att, g_att);
    cudaGetSymbolAddress((void**)&wv,  g_wv);
    cudaGetSymbolAddress((void**)&bv2, g_bv2);

    cudaFuncSetAttribute(gemm_smallmm, cudaFuncAttributeMaxDynamicSharedMemorySize, SMEM_TOTAL);
    cudaFuncSetAttribute(gemm_projs,   cudaFuncAttributeMaxDynamicSharedMemorySize, SMEM_TOTAL);
    cudaFuncSetAttribute(gemm_z,       cudaFuncAttributeMaxDynamicSharedMemorySize, SMEM_TOTAL);
    cudaFuncSetAttribute(gemm_final,   cudaFuncAttributeMaxDynamicSharedMemorySize, SMEM_TOTAL);

    // 1: small vectors wv, bv2
    smallvec<<<dim3(8, 2), 128>>>(Wk, bq, Wo, bv, wv, bv2);

    // 2: converts x->xb, Wo->wob
    {
        int gx = (NTOK * DIM / 4 + 255) / 256;
        conv2<<<dim3(gx, 2), 256>>>(x, Wo, xb, wob);
    }

    // 3: transpose-converts Wq^T, Wk^T, Wv^T
    tconv<<<dim3(32, 32, 3), dim3(32, 8)>>>(Wq, Wk, Wv, wqT, wkT, wvT);

    // 4: Mt = NT(WkT, WqT), W2 = NT(Wo, WvT)
    gemm_smallmm<<<dim3(8, 8, 2), 256, SMEM_TOTAL>>>();

    // 5: y = NT(xb, Mt) + wv;  PT = NT(W2, xb) + bv2[row]
    gemm_projs<<<dim3(64, 8, 2), 256, SMEM_TOTAL>>>();

    // 6: att = exp((y @ xb^T) * inv_scale)
    gemm_z<<<dim3(64, 64), 128, SMEM_TOTAL>>>(y, xb, att);

    // 7: out = (att @ PT^T) / rowsum + bo + x   [fused rowsum]
    gemm_final<<<dim3(8, 64), 128, SMEM_TOTAL>>>(att, PT, bo, x, out);
}

// round 16
// speedup vs baseline: 1.0722x; 1.0722x over previous
#include <cuda_runtime.h>
#include <cuda_bf16.h>
#include <math.h>
#include <stdint.h>

#define NTOK 8192
#define DIM  1024
#define INV_SCALE 0.08838834764831843f   // 1/sqrt(128)

// ---------------------------------------------------------------------------
// Scratch (device globals; no allocation allowed)
// ---------------------------------------------------------------------------
__device__ __nv_bfloat16 g_xb[(size_t)NTOK * DIM];
__device__ __nv_bfloat16 g_wob[(size_t)DIM * DIM];
__device__ __nv_bfloat16 g_wqT[(size_t)DIM * DIM];
__device__ __nv_bfloat16 g_wkT[(size_t)DIM * DIM];
__device__ __nv_bfloat16 g_wvT[(size_t)DIM * DIM];
__device__ __nv_bfloat16 g_Mt[(size_t)DIM * DIM];    // (Wq^T Wk)^T
__device__ __nv_bfloat16 g_W2[(size_t)DIM * DIM];    // Wo*Wv
__device__ __nv_bfloat16 g_y[(size_t)NTOK * DIM];    // x*M
__device__ __nv_bfloat16 g_PT[(size_t)DIM * NTOK];   // (v*Wo^T)^T
__device__ __nv_bfloat16 g_att[(size_t)NTOK * NTOK]; // exp((z+v_j)*inv_scale)
__device__ float g_rs[NTOK];                         // row sums of exp
__device__ float g_wv[DIM];                          // Wk^T * bq
__device__ float g_bv2[DIM];                         // Wo * bv
__device__ float g_v[NTOK];                          // x * wv

// ---------------------------------------------------------------------------
// Helpers
// ---------------------------------------------------------------------------
__device__ __forceinline__ uint32_t smem_u32(const void* p) {
    uint32_t a;
    asm("{ .reg .u64 t; cvta.to.shared.u64 t, %1; cvt.u32.u64 %0, t; }" : "=r"(a) : "l"(p));
    return a;
}
__device__ __forceinline__ uint32_t swz(uint32_t x) { return x ^ ((x >> 3) & 0x70); }

__device__ __forceinline__ void cp16(uint32_t saddr, const void* g) {
    asm volatile("cp.async.cg.shared.global [%0], [%1], 16;\n" :: "r"(saddr), "l"(g));
}
__device__ __forceinline__ void cp_commit() { asm volatile("cp.async.commit_group;\n" ::); }
template <int N> __device__ __forceinline__ void cp_wait() {
    asm volatile("cp.async.wait_group %0;\n" :: "n"(N));
}

__device__ __forceinline__ void ldsm_x4(uint32_t addr, uint32_t* r) {
    asm volatile("ldmatrix.sync.aligned.m8n8.x4.shared.b16 {%0,%1,%2,%3}, [%4];"
        : "=r"(r[0]), "=r"(r[1]), "=r"(r[2]), "=r"(r[3]) : "r"(addr));
}

__device__ __forceinline__ void mma_bf16(float* c, const uint32_t* a, const uint32_t* b) {
    asm volatile("mma.sync.aligned.m16n8k16.row.col.f32.bf16.bf16.f32 "
        "{%0,%1,%2,%3}, {%4,%5,%6,%7}, {%8,%9}, {%0,%1,%2,%3};"
        : "+f"(c[0]), "+f"(c[1]), "+f"(c[2]), "+f"(c[3])
        : "r"(a[0]), "r"(a[1]), "r"(a[2]), "r"(a[3]), "r"(b[0]), "r"(b[1]));
}

__device__ __forceinline__ uint32_t pack_bf16(float lo, float hi) {
    uint32_t r;
    asm("cvt.rn.bf16x2.f32 %0, %1, %2;" : "=r"(r) : "f"(hi), "f"(lo));
    return r;
}

#define BM 128
#define BN 128
#define BK 64
#define T_ST_BYTES (128 * 128)
#define SMEM_B_OFF (3 * T_ST_BYTES)
#define SMEM_TOTAL (6 * T_ST_BYTES)              // 98304

// ---------------------------------------------------------------------------
// 256-thread body: 8 warps (2M x 4N), warp tile 64x32, 2 CTAs/SM.
// bf16 output with optional col bias and/or row bias.
// ---------------------------------------------------------------------------
__device__ __forceinline__ void gemm_body_b16(
    const __nv_bfloat16* __restrict__ A,
    const __nv_bfloat16* __restrict__ B,
    const float* __restrict__ cbias,   // per-col, may be null
    const float* __restrict__ rbias,   // per-row, may be null
    __nv_bfloat16* __restrict__ C,
    int Nn, int K, int bm, int bn, char* smem)
{
    const uint32_t sb = smem_u32(smem);
    const int tid = threadIdx.x, lane = tid & 31, wid = tid >> 5;
    const int wn = wid & 3, wm = wid >> 2;

    float acc[4][4][4];
    #pragma unroll
    for (int i = 0; i < 4; i++)
        #pragma unroll
        for (int j = 0; j < 4; j++)
            #pragma unroll
            for (int q = 0; q < 4; q++) acc[i][j][q] = 0.0f;

    const int KT = K / BK;

    auto load_stage = [&](int s, int kt) {
        const int k0 = kt * BK;
        const uint32_t ab = sb + s * T_ST_BYTES;
        const __nv_bfloat16* Ag = A + (size_t)bm * K + k0;
        #pragma unroll
        for (int i = 0; i < 4; i++) {
            int c = tid + (i << 8);
            int r = c >> 3, kc = c & 7;
            cp16(ab + swz((r << 7) + (kc << 4)), Ag + (size_t)r * K + (kc << 3));
        }
        const uint32_t bb = sb + SMEM_B_OFF + s * T_ST_BYTES;
        const __nv_bfloat16* Bg = B + (size_t)bn * K + k0;
        #pragma unroll
        for (int i = 0; i < 4; i++) {
            int c = tid + (i << 8);
            int r = c >> 3, kc = c & 7;
            cp16(bb + swz((r << 7) + (kc << 4)), Bg + (size_t)r * K + (kc << 3));
        }
        cp_commit();
    };

    load_stage(0, 0);
    load_stage(1, 1);

    const int g = lane >> 3, r8 = lane & 7;
    const int a_row = wm * 64 + (g & 1) * 8 + r8;
    const int a_kb  = (g >> 1) * 16;
    const int b_row = wn * 32 + (g >> 1) * 8 + r8;
    const int b_kb  = (g & 1) * 16;

    int s = 0;
    for (int kt = 0; kt < KT; kt++) {
        if (kt + 1 < KT) cp_wait<1>(); else cp_wait<0>();
        __syncthreads();

        if (kt + 2 < KT) load_stage((kt + 2) % 3, kt + 2);

        const uint32_t abase = sb + s * T_ST_BYTES;
        const uint32_t bbase = sb + SMEM_B_OFF + s * T_ST_BYTES;

        #pragma unroll
        for (int ks = 0; ks < 4; ks++) {
            uint32_t a[4][4], b[2][4];
            #pragma unroll
            for (int mt = 0; mt < 4; mt++)
                ldsm_x4(abase + swz(((a_row + mt * 16) << 7) + ks * 32 + a_kb), a[mt]);
            #pragma unroll
            for (int np = 0; np < 2; np++)
                ldsm_x4(bbase + swz(((b_row + np * 16) << 7) + ks * 32 + b_kb), b[np]);
            #pragma unroll
            for (int mt = 0; mt < 4; mt++)
                #pragma unroll
                for (int np = 0; np < 2; np++) {
                    mma_bf16(acc[mt][np * 2],     a[mt], &b[np][0]);
                    mma_bf16(acc[mt][np * 2 + 1], a[mt], &b[np][2]);
                }
        }
        s++; if (s == 3) s = 0;
    }

    const int lr = lane >> 2, lc = (lane & 3) * 2;

    #pragma unroll
    for (int mt = 0; mt < 4; mt++) {
        #pragma unroll
        for (int h = 0; h < 2; h++) {
            const int row = bm + wm * 64 + mt * 16 + h * 8 + lr;
            const float rb = rbias ? rbias[row] : 0.0f;
            #pragma unroll
            for (int nt = 0; nt < 4; nt++) {
                const int col = bn + wn * 32 + nt * 8 + lc;
                float v0 = acc[mt][nt][h * 2]     + rb;
                float v1 = acc[mt][nt][h * 2 + 1] + rb;
                if (cbias) { v0 += cbias[col]; v1 += cbias[col + 1]; }
                uint32_t* dst = (uint32_t*)(C + (size_t)row * Nn + col);
                *dst = pack_bf16(v0, v1);
            }
        }
    }
}

// small matrix products: z=0: Mt = NT(WkT, WqT); z=1: W2 = NT(Wo, WvT)
__global__ __launch_bounds__(256, 2)
void gemm_smallmm()
{
    extern __shared__ char smem[];
    const __nv_bfloat16* A = (blockIdx.z == 0) ? g_wkT : g_wob;
    const __nv_bfloat16* B = (blockIdx.z == 0) ? g_wqT : g_wvT;
    __nv_bfloat16* C       = (blockIdx.z == 0) ? g_Mt  : g_W2;
    gemm_body_b16(A, B, nullptr, nullptr, C, DIM, DIM,
                  blockIdx.y * BM, blockIdx.x * BN, smem);
}

// projections: z=0: y = NT(xb, Mt); z=1: PT = NT(W2, xb) + bv2[row]
__global__ __launch_bounds__(256, 2)
void gemm_projs()
{
    extern __shared__ char smem[];
    if (blockIdx.z == 0) {
        gemm_body_b16(g_xb, g_Mt, nullptr, nullptr, g_y, DIM, DIM,
                      blockIdx.x * BM, blockIdx.y * BN, smem);
    } else {
        gemm_body_b16(g_W2, g_xb, nullptr, g_bv2, g_PT, NTOK, DIM,
                      blockIdx.y * BM, blockIdx.x * BN, smem);
    }
}

// ---------------------------------------------------------------------------
// 128-thread big-GEMM body: 4 warps (2M x 2N), warp tile 64x64,
// frag double-buffering, 2 CTAs/SM. EPI 0 = exp((acc+v[col])*scale) -> bf16
//                                   EPI 1 = acc*rcp + bo[col] + res  -> f32
// ---------------------------------------------------------------------------
template <int EPI>
__global__ __launch_bounds__(128, 2)
void gemm_two(const __nv_bfloat16* __restrict__ A,
              const __nv_bfloat16* __restrict__ B,
              const float* __restrict__ vvec,
              const float* __restrict__ rs,
              const float* __restrict__ bias,
              const float* __restrict__ res,
              void* __restrict__ Cv,
              int Nn, int K)
{
    extern __shared__ char smem[];
    const uint32_t sb = smem_u32(smem);
    const int tid = threadIdx.x, lane = tid & 31, wid = tid >> 5;
    const int wn = wid & 1, wm = wid >> 1;
    const int bm = blockIdx.y * BM, bn = blockIdx.x * BN;

    float acc[4][8][4];
    #pragma unroll
    for (int i = 0; i < 4; i++)
        #pragma unroll
        for (int j = 0; j < 8; j++)
            #pragma unroll
            for (int q = 0; q < 4; q++) acc[i][j][q] = 0.0f;

    const int KT = K / BK;

    auto load_stage = [&](int s, int kt) {
        const int k0 = kt * BK;
        const uint32_t ab = sb + s * T_ST_BYTES;
        const __nv_bfloat16* Ag = A + (size_t)bm * K + k0;
        #pragma unroll
        for (int i = 0; i < 8; i++) {
            int c = tid + (i << 7);
            int r = c >> 3, kc = c & 7;
            cp16(ab + swz((r << 7) + (kc << 4)), Ag + (size_t)r * K + (kc << 3));
        }
        const uint32_t bb = sb + SMEM_B_OFF + s * T_ST_BYTES;
        const __nv_bfloat16* Bg = B + (size_t)bn * K + k0;
        #pragma unroll
        for (int i = 0; i < 8; i++) {
            int c = tid + (i << 7);
            int r = c >> 3, kc = c & 7;
            cp16(bb + swz((r << 7) + (kc << 4)), Bg + (size_t)r * K + (kc << 3));
        }
        cp_commit();
    };

    load_stage(0, 0);
    load_stage(1, 1);

    const int g = lane >> 3, r8 = lane & 7;
    const int a_row = wm * 64 + (g & 1) * 8 + r8;     // + mt*16
    const int a_kb  = (g >> 1) * 16;                  // + ks*32
    const int b_row = wn * 64 + (g >> 1) * 8 + r8;    // + np*16
    const int b_kb  = (g & 1) * 16;                   // + ks*32

    uint32_t a[2][4][4], b[2][4][4];

    int s = 0;
    for (int kt = 0; kt < KT; kt++) {
        if (kt + 1 < KT) cp_wait<1>(); else cp_wait<0>();
        __syncthreads();

        if (kt + 2 < KT) load_stage((kt + 2) % 3, kt + 2);

        const uint32_t abase = sb + s * T_ST_BYTES;
        const uint32_t bbase = sb + SMEM_B_OFF + s * T_ST_BYTES;

        // prime frags for ks=0
        #pragma unroll
        for (int mt = 0; mt < 4; mt++)
            ldsm_x4(abase + swz(((a_row + mt * 16) << 7) + a_kb), a[0][mt]);
        #pragma unroll
        for (int np = 0; np < 4; np++)
            ldsm_x4(bbase + swz(((b_row + np * 16) << 7) + b_kb), b[0][np]);

        #pragma unroll
        for (int ks = 0; ks < 4; ks++) {
            const int cur = ks & 1;
            if (ks < 3) {
                const int nxt = cur ^ 1;
                #pragma unroll
                for (int mt = 0; mt < 4; mt++)
                    ldsm_x4(abase + swz(((a_row + mt * 16) << 7) + (ks + 1) * 32 + a_kb), a[nxt][mt]);
                #pragma unroll
                for (int np = 0; np < 4; np++)
                    ldsm_x4(bbase + swz(((b_row + np * 16) << 7) + (ks + 1) * 32 + b_kb), b[nxt][np]);
            }
            #pragma unroll
            for (int mt = 0; mt < 4; mt++)
                #pragma unroll
                for (int np = 0; np < 4; np++) {
                    mma_bf16(acc[mt][np * 2],     a[cur][mt], &b[cur][np][0]);
                    mma_bf16(acc[mt][np * 2 + 1], a[cur][mt], &b[cur][np][2]);
                }
        }
        s++; if (s == 3) s = 0;
    }

    // ---- epilogue ----
    const int lr = lane >> 2, lc = (lane & 3) * 2;

    #pragma unroll
    for (int mt = 0; mt < 4; mt++) {
        #pragma unroll
        for (int h = 0; h < 2; h++) {
            const int row = bm + wm * 64 + mt * 16 + h * 8 + lr;
            float rcp = 0.0f;
            if (EPI == 1) rcp = 1.0f / rs[row];
            #pragma unroll
            for (int nt = 0; nt < 8; nt++) {
                const int col = bn + wn * 64 + nt * 8 + lc;
                float v0 = acc[mt][nt][h * 2];
                float v1 = acc[mt][nt][h * 2 + 1];
                if (EPI == 0) {
                    v0 = __expf((v0 + vvec[col])     * INV_SCALE);
                    v1 = __expf((v1 + vvec[col + 1]) * INV_SCALE);
                    uint32_t* dst = (uint32_t*)((__nv_bfloat16*)Cv + (size_t)row * Nn + col);
                    *dst = pack_bf16(v0, v1);
                } else {
                    const float2 rv = *(const float2*)(res + (size_t)row * Nn + col);
                    v0 = v0 * rcp + bias[col]     + rv.x;
                    v1 = v1 * rcp + bias[col + 1] + rv.y;
                    float2* dst = (float2*)((float*)Cv + (size_t)row * Nn + col);
                    *dst = make_float2(v0, v1);
                }
            }
        }
    }
}

// ---------------------------------------------------------------------------
// small vectors: y=0: wv[e] = sum_a Wk[a,e]*bq[a]; y=1: bv2[d] = Wo[d,:].bv
// ---------------------------------------------------------------------------
__global__ __launch_bounds__(128)
void smallvec(const float* __restrict__ Wk, const float* __restrict__ bq,
              const float* __restrict__ Wo, const float* __restrict__ bv,
              float* __restrict__ wv, float* __restrict__ bv2)
{
    const int i = blockIdx.x * 128 + threadIdx.x;
    if (blockIdx.y == 0) {
        float s = 0.0f;
        for (int a = 0; a < DIM; a++) s += Wk[(size_t)a * DIM + i] * bq[a];
        wv[i] = s;
    } else {
        float s = 0.0f;
        for (int e = 0; e < DIM; e++) s += Wo[(size_t)i * DIM + e] * bv[e];
        bv2[i] = s;
    }
}

// v[i] = x[i,:] . wv   (warp per row, deterministic)
__global__ __launch_bounds__(256)
void gemv_v(const float* __restrict__ x, const float* __restrict__ wv,
            float* __restrict__ v)
{
    const int lane = threadIdx.x & 31, warp = threadIdx.x >> 5;
    const int row = blockIdx.x * 8 + warp;
    const float* p = x + (size_t)row * DIM;
    float s = 0.0f;
    #pragma unroll
    for (int k = 0; k < 32; k++) s += p[lane + k * 32] * wv[lane + k * 32];
    #pragma unroll
    for (int o = 16; o > 0; o >>= 1) s += __shfl_xor_sync(0xFFFFFFFF, s, o);
    if (lane == 0) v[row] = s;
}

// converts: y=0: x -> xb (bf16), y=1: Wo -> wob
__global__ __launch_bounds__(256)
void conv2(const float* __restrict__ x, const float* __restrict__ Wo,
           __nv_bfloat16* __restrict__ xo, __nv_bfloat16* __restrict__ oo)
{
    const float* in; __nv_bfloat16* out; int n4;
    if (blockIdx.y == 0) { in = x;  out = xo; n4 = NTOK * DIM / 4; }
    else                 { in = Wo; out = oo; n4 = DIM * DIM / 4; }
    int i = blockIdx.x * blockDim.x + threadIdx.x;
    if (i >= n4) return;
    float4 v = reinterpret_cast<const float4*>(in)[i];
    uint2 o;
    o.x = pack_bf16(v.x, v.y);
    o.y = pack_bf16(v.z, v.w);
    reinterpret_cast<uint2*>(out)[i] = o;
}

// transpose-convert: out[d,f] = bf16(W[f,d]), 1024x1024, z picks Wq/Wk/Wv
__global__ __launch_bounds__(256)
void tconv(const float* __restrict__ Wq, const float* __restrict__ Wk,
           const float* __restrict__ Wv,
           __nv_bfloat16* __restrict__ oq, __nv_bfloat16* __restrict__ ok,
           __nv_bfloat16* __restrict__ ov)
{
    __shared__ float t[32][33];
    const float* in; __nv_bfloat16* out;
    if (blockIdx.z == 0)      { in = Wq; out = oq; }
    else if (blockIdx.z == 1) { in = Wk; out = ok; }
    else                      { in = Wv; out = ov; }
    const int bx = blockIdx.x * 32;   // output row block (input col)
    const int by = blockIdx.y * 32;   // input row block
    const int x = threadIdx.x, y = threadIdx.y;
    #pragma unroll
    for (int i = 0; i < 32; i += 8)
        t[y + i][x] = in[(size_t)(by + y + i) * DIM + bx + x];
    __syncthreads();
    #pragma unroll
    for (int i = 0; i < 32; i += 8)
        out[(size_t)(bx + y + i) * DIM + by + x] = __float2bfloat16(t[x][y + i]);
}

// ---------------------------------------------------------------------------
// Row sums of att (bf16, unnormalized exp) -> fp32. Deterministic tree.
// ---------------------------------------------------------------------------
__global__ __launch_bounds__(256)
void rowsum_kernel(const __nv_bfloat16* __restrict__ att, float* __restrict__ rs)
{
    const int row = blockIdx.x;
    const uint4* p = reinterpret_cast<const uint4*>(att + (size_t)row * NTOK);
    const int tid = threadIdx.x, lane = tid & 31, warp = tid >> 5;
    __shared__ float red[8];

    float s = 0.0f;
    #pragma unroll
    for (int i = 0; i < 4; i++) {
        uint4 u = p[tid + i * 256];
        float2 f0 = __bfloat1622float2(*reinterpret_cast<__nv_bfloat162*>(&u.x));
        float2 f1 = __bfloat1622float2(*reinterpret_cast<__nv_bfloat162*>(&u.y));
        float2 f2 = __bfloat1622float2(*reinterpret_cast<__nv_bfloat162*>(&u.z));
        float2 f3 = __bfloat1622float2(*reinterpret_cast<__nv_bfloat162*>(&u.w));
        s += ((f0.x + f0.y) + (f1.x + f1.y)) + ((f2.x + f2.y) + (f3.x + f3.y));
    }
    #pragma unroll
    for (int o = 16; o > 0; o >>= 1) s += __shfl_xor_sync(0xFFFFFFFF, s, o);
    if (lane == 0) red[warp] = s;
    __syncthreads();
    if (warp == 0) {
        s = red[lane & 7];
        #pragma unroll
        for (int o = 4; o > 0; o >>= 1) s += __shfl_xor_sync(0xFFFFFFFF, s, o);
        if (lane == 0) rs[row] = s;
    }
}

// ---------------------------------------------------------------------------
// Launch
// ---------------------------------------------------------------------------
extern "C" void kernel_launch(void* const* d_in, const int* in_sizes, int n_in,
                              void* d_out, int out_size)
{
    const float* x  = (const float*)d_in[0];
    const float* Wq = (const float*)d_in[1];
    const float* bq = (const float*)d_in[2];
    const float* Wk = (const float*)d_in[3];
    const float* bk = (const float*)d_in[4];
    const float* Wv = (const float*)d_in[5];
    const float* bv = (const float*)d_in[6];
    const float* Wo = (const float*)d_in[7];
    const float* bo = (const float*)d_in[8];
    float* out = (float*)d_out;
    (void)bk;  // cancels in softmax (row-constant)

    __nv_bfloat16 *xb, *wob, *wqT, *wkT, *wvT, *Mt, *W2, *y, *PT, *att;
    float *rs, *wv, *bv2, *vv;
    cudaGetSymbolAddress((void**)&xb,  g_xb);
    cudaGetSymbolAddress((void**)&wob, g_wob);
    cudaGetSymbolAddress((void**)&wqT, g_wqT);
    cudaGetSymbolAddress((void**)&wkT, g_wkT);
    cudaGetSymbolAddress((void**)&wvT, g_wvT);
    cudaGetSymbolAddress((void**)&Mt,  g_Mt);
    cudaGetSymbolAddress((void**)&W2,  g_W2);
    cudaGetSymbolAddress((void**)&y,   g_y);
    cudaGetSymbolAddress((void**)&PT,  g_PT);
    cudaGetSymbolAddress((void**)&att, g_att);
    cudaGetSymbolAddress((void**)&rs,  g_rs);
    cudaGetSymbolAddress((void**)&wv,  g_wv);
    cudaGetSymbolAddress((void**)&bv2, g_bv2);
    cudaGetSymbolAddress((void**)&vv,  g_v);

    cudaFuncSetAttribute(gemm_smallmm, cudaFuncAttributeMaxDynamicSharedMemorySize, SMEM_TOTAL);
    cudaFuncSetAttribute(gemm_projs,   cudaFuncAttributeMaxDynamicSharedMemorySize, SMEM_TOTAL);
    cudaFuncSetAttribute(gemm_two<0>,  cudaFuncAttributeMaxDynamicSharedMemorySize, SMEM_TOTAL);
    cudaFuncSetAttribute(gemm_two<1>,  cudaFuncAttributeMaxDynamicSharedMemorySize, SMEM_TOTAL);

    // 1: small vectors wv, bv2
    smallvec<<<dim3(8, 2), 128>>>(Wk, bq, Wo, bv, wv, bv2);

    // 2: converts x->xb, Wo->wob
    {
        int gx = (NTOK * DIM / 4 + 255) / 256;
        conv2<<<dim3(gx, 2), 256>>>(x, Wo, xb, wob);
    }

    // 3: transpose-converts Wq^T, Wk^T, Wv^T
    tconv<<<dim3(32, 32, 3), dim3(32, 8)>>>(Wq, Wk, Wv, wqT, wkT, wvT);

    // 4: v = x . wv
    gemv_v<<<NTOK / 8, 256>>>(x, wv, vv);

    // 5: Mt = NT(WkT, WqT), W2 = NT(Wo, WvT)
    gemm_smallmm<<<dim3(8, 8, 2), 256, SMEM_TOTAL>>>();

    // 6: y = NT(xb, Mt);  PT = NT(W2, xb) + bv2[row]
    gemm_projs<<<dim3(64, 8, 2), 256, SMEM_TOTAL>>>();

    // 7: att = exp((y @ xb^T + v_j) * inv_scale)
    gemm_two<0><<<dim3(64, 64), 128, SMEM_TOTAL>>>(y, xb, vv, nullptr, nullptr, nullptr,
                                                   att, NTOK, DIM);

    // 8: rs[row] = sum of att row
    rowsum_kernel<<<NTOK, 256>>>(att, rs);

    // 9: out = (att @ PT^T) * (1/rs) + bo + x
    gemm_two<1><<<dim3(8, 64), 128, SMEM_TOTAL>>>(att, PT, nullptr, rs, bo, x,
                                                  out, DIM, NTOK);
}

// round 17
// speedup vs baseline: 1.1002x; 1.0261x over previous
#include <cuda_runtime.h>
#include <cuda_bf16.h>
#include <math.h>
#include <stdint.h>

#define NTOK 8192
#define DIM  1024
#define INV_SCALE 0.08838834764831843f   // 1/sqrt(128)
#define KSPLIT 4
#define KCHUNK (NTOK / KSPLIT)            // 2048

// ---------------------------------------------------------------------------
// Scratch (device globals; no allocation allowed)
// ---------------------------------------------------------------------------
__device__ __nv_bfloat16 g_xb[(size_t)NTOK * DIM];
__device__ __nv_bfloat16 g_wob[(size_t)DIM * DIM];
__device__ __nv_bfloat16 g_wqT[(size_t)DIM * DIM];
__device__ __nv_bfloat16 g_wkT[(size_t)DIM * DIM];
__device__ __nv_bfloat16 g_wvT[(size_t)DIM * DIM];
__device__ __nv_bfloat16 g_Mt[(size_t)DIM * DIM];    // (Wq^T Wk)^T
__device__ __nv_bfloat16 g_W2[(size_t)DIM * DIM];    // Wo*Wv
__device__ __nv_bfloat16 g_y[(size_t)NTOK * DIM];    // x*M
__device__ __nv_bfloat16 g_PT[(size_t)DIM * NTOK];   // (v*Wo^T)^T
__device__ __nv_bfloat16 g_att[(size_t)NTOK * NTOK]; // exp((z+v_j)*inv_scale)
__device__ float g_part[(size_t)KSPLIT * NTOK * DIM];// split-K partials (128 MB)
__device__ float g_rs[NTOK];                         // row sums of exp
__device__ float g_wv[DIM];                          // Wk^T * bq
__device__ float g_bv2[DIM];                         // Wo * bv
__device__ float g_v[NTOK];                          // x * wv

// ---------------------------------------------------------------------------
// Helpers
// ---------------------------------------------------------------------------
__device__ __forceinline__ uint32_t smem_u32(const void* p) {
    uint32_t a;
    asm("{ .reg .u64 t; cvta.to.shared.u64 t, %1; cvt.u32.u64 %0, t; }" : "=r"(a) : "l"(p));
    return a;
}
__device__ __forceinline__ uint32_t swz(uint32_t x) { return x ^ ((x >> 3) & 0x70); }

__device__ __forceinline__ void cp16(uint32_t saddr, const void* g) {
    asm volatile("cp.async.cg.shared.global [%0], [%1], 16;\n" :: "r"(saddr), "l"(g));
}
__device__ __forceinline__ void cp_commit() { asm volatile("cp.async.commit_group;\n" ::); }
template <int N> __device__ __forceinline__ void cp_wait() {
    asm volatile("cp.async.wait_group %0;\n" :: "n"(N));
}

__device__ __forceinline__ void ldsm_x4(uint32_t addr, uint32_t* r) {
    asm volatile("ldmatrix.sync.aligned.m8n8.x4.shared.b16 {%0,%1,%2,%3}, [%4];"
        : "=r"(r[0]), "=r"(r[1]), "=r"(r[2]), "=r"(r[3]) : "r"(addr));
}

__device__ __forceinline__ void mma_bf16(float* c, const uint32_t* a, const uint32_t* b) {
    asm volatile("mma.sync.aligned.m16n8k16.row.col.f32.bf16.bf16.f32 "
        "{%0,%1,%2,%3}, {%4,%5,%6,%7}, {%8,%9}, {%0,%1,%2,%3};"
        : "+f"(c[0]), "+f"(c[1]), "+f"(c[2]), "+f"(c[3])
        : "r"(a[0]), "r"(a[1]), "r"(a[2]), "r"(a[3]), "r"(b[0]), "r"(b[1]));
}

__device__ __forceinline__ uint32_t pack_bf16(float lo, float hi) {
    uint32_t r;
    asm("cvt.rn.bf16x2.f32 %0, %1, %2;" : "=r"(r) : "f"(hi), "f"(lo));
    return r;
}

#define BM 128
#define BN 128
#define BK 64
#define T_ST_BYTES (128 * 128)
#define SMEM_B_OFF (3 * T_ST_BYTES)
#define SMEM_TOTAL (6 * T_ST_BYTES)              // 98304

// ---------------------------------------------------------------------------
// 256-thread body: 8 warps (2M x 4N), warp tile 64x32, 2 CTAs/SM.
// ---------------------------------------------------------------------------
__device__ __forceinline__ void gemm_body_b16(
    const __nv_bfloat16* __restrict__ A,
    const __nv_bfloat16* __restrict__ B,
    const float* __restrict__ cbias,
    const float* __restrict__ rbias,
    __nv_bfloat16* __restrict__ C,
    int Nn, int K, int bm, int bn, char* smem)
{
    const uint32_t sb = smem_u32(smem);
    const int tid = threadIdx.x, lane = tid & 31, wid = tid >> 5;
    const int wn = wid & 3, wm = wid >> 2;

    float acc[4][4][4];
    #pragma unroll
    for (int i = 0; i < 4; i++)
        #pragma unroll
        for (int j = 0; j < 4; j++)
            #pragma unroll
            for (int q = 0; q < 4; q++) acc[i][j][q] = 0.0f;

    const int KT = K / BK;

    auto load_stage = [&](int s, int kt) {
        const int k0 = kt * BK;
        const uint32_t ab = sb + s * T_ST_BYTES;
        const __nv_bfloat16* Ag = A + (size_t)bm * K + k0;
        #pragma unroll
        for (int i = 0; i < 4; i++) {
            int c = tid + (i << 8);
            int r = c >> 3, kc = c & 7;
            cp16(ab + swz((r << 7) + (kc << 4)), Ag + (size_t)r * K + (kc << 3));
        }
        const uint32_t bb = sb + SMEM_B_OFF + s * T_ST_BYTES;
        const __nv_bfloat16* Bg = B + (size_t)bn * K + k0;
        #pragma unroll
        for (int i = 0; i < 4; i++) {
            int c = tid + (i << 8);
            int r = c >> 3, kc = c & 7;
            cp16(bb + swz((r << 7) + (kc << 4)), Bg + (size_t)r * K + (kc << 3));
        }
        cp_commit();
    };

    load_stage(0, 0);
    load_stage(1, 1);

    const int g = lane >> 3, r8 = lane & 7;
    const int a_row = wm * 64 + (g & 1) * 8 + r8;
    const int a_kb  = (g >> 1) * 16;
    const int b_row = wn * 32 + (g >> 1) * 8 + r8;
    const int b_kb  = (g & 1) * 16;

    int s = 0;
    for (int kt = 0; kt < KT; kt++) {
        if (kt + 1 < KT) cp_wait<1>(); else cp_wait<0>();
        __syncthreads();

        if (kt + 2 < KT) load_stage((kt + 2) % 3, kt + 2);

        const uint32_t abase = sb + s * T_ST_BYTES;
        const uint32_t bbase = sb + SMEM_B_OFF + s * T_ST_BYTES;

        #pragma unroll
        for (int ks = 0; ks < 4; ks++) {
            uint32_t a[4][4], b[2][4];
            #pragma unroll
            for (int mt = 0; mt < 4; mt++)
                ldsm_x4(abase + swz(((a_row + mt * 16) << 7) + ks * 32 + a_kb), a[mt]);
            #pragma unroll
            for (int np = 0; np < 2; np++)
                ldsm_x4(bbase + swz(((b_row + np * 16) << 7) + ks * 32 + b_kb), b[np]);
            #pragma unroll
            for (int mt = 0; mt < 4; mt++)
                #pragma unroll
                for (int np = 0; np < 2; np++) {
                    mma_bf16(acc[mt][np * 2],     a[mt], &b[np][0]);
                    mma_bf16(acc[mt][np * 2 + 1], a[mt], &b[np][2]);
                }
        }
        s++; if (s == 3) s = 0;
    }

    const int lr = lane >> 2, lc = (lane & 3) * 2;

    #pragma unroll
    for (int mt = 0; mt < 4; mt++) {
        #pragma unroll
        for (int h = 0; h < 2; h++) {
            const int row = bm + wm * 64 + mt * 16 + h * 8 + lr;
            const float rb = rbias ? rbias[row] : 0.0f;
            #pragma unroll
            for (int nt = 0; nt < 4; nt++) {
                const int col = bn + wn * 32 + nt * 8 + lc;
                float v0 = acc[mt][nt][h * 2]     + rb;
                float v1 = acc[mt][nt][h * 2 + 1] + rb;
                if (cbias) { v0 += cbias[col]; v1 += cbias[col + 1]; }
                uint32_t* dst = (uint32_t*)(C + (size_t)row * Nn + col);
                *dst = pack_bf16(v0, v1);
            }
        }
    }
}

// small matrix products: z=0: Mt = NT(WkT, WqT); z=1: W2 = NT(Wo, WvT)
__global__ __launch_bounds__(256, 2)
void gemm_smallmm()
{
    extern __shared__ char smem[];
    const __nv_bfloat16* A = (blockIdx.z == 0) ? g_wkT : g_wob;
    const __nv_bfloat16* B = (blockIdx.z == 0) ? g_wqT : g_wvT;
    __nv_bfloat16* C       = (blockIdx.z == 0) ? g_Mt  : g_W2;
    gemm_body_b16(A, B, nullptr, nullptr, C, DIM, DIM,
                  blockIdx.y * BM, blockIdx.x * BN, smem);
}

// projections: z=0: y = NT(xb, Mt); z=1: PT = NT(W2, xb) + bv2[row]
__global__ __launch_bounds__(256, 2)
void gemm_projs()
{
    extern __shared__ char smem[];
    if (blockIdx.z == 0) {
        gemm_body_b16(g_xb, g_Mt, nullptr, nullptr, g_y, DIM, DIM,
                      blockIdx.x * BM, blockIdx.y * BN, smem);
    } else {
        gemm_body_b16(g_W2, g_xb, nullptr, g_bv2, g_PT, NTOK, DIM,
                      blockIdx.y * BM, blockIdx.x * BN, smem);
    }
}

// ---------------------------------------------------------------------------
// z GEMM (128 threads, 4 warps 2Mx2N, warp 64x64, frag double-buffer):
// att = exp((y @ xb^T + v[col]) * inv_scale)
// ---------------------------------------------------------------------------
__global__ __launch_bounds__(128, 2)
void gemm_z(const __nv_bfloat16* __restrict__ A,
            const __nv_bfloat16* __restrict__ B,
            const float* __restrict__ vvec,
            __nv_bfloat16* __restrict__ att)
{
    extern __shared__ char smem[];
    const uint32_t sb = smem_u32(smem);
    const int tid = threadIdx.x, lane = tid & 31, wid = tid >> 5;
    const int wn = wid & 1, wm = wid >> 1;
    const int bm = blockIdx.y * BM, bn = blockIdx.x * BN;
    const int K = DIM, KT = K / BK;

    float acc[4][8][4];
    #pragma unroll
    for (int i = 0; i < 4; i++)
        #pragma unroll
        for (int j = 0; j < 8; j++)
            #pragma unroll
            for (int q = 0; q < 4; q++) acc[i][j][q] = 0.0f;

    auto load_stage = [&](int s, int kt) {
        const int k0 = kt * BK;
        const uint32_t ab = sb + s * T_ST_BYTES;
        const __nv_bfloat16* Ag = A + (size_t)bm * K + k0;
        #pragma unroll
        for (int i = 0; i < 8; i++) {
            int c = tid + (i << 7);
            int r = c >> 3, kc = c & 7;
            cp16(ab + swz((r << 7) + (kc << 4)), Ag + (size_t)r * K + (kc << 3));
        }
        const uint32_t bb = sb + SMEM_B_OFF + s * T_ST_BYTES;
        const __nv_bfloat16* Bg = B + (size_t)bn * K + k0;
        #pragma unroll
        for (int i = 0; i < 8; i++) {
            int c = tid + (i << 7);
            int r = c >> 3, kc = c & 7;
            cp16(bb + swz((r << 7) + (kc << 4)), Bg + (size_t)r * K + (kc << 3));
        }
        cp_commit();
    };

    load_stage(0, 0);
    load_stage(1, 1);

    const int g = lane >> 3, r8 = lane & 7;
    const int a_row = wm * 64 + (g & 1) * 8 + r8;
    const int a_kb  = (g >> 1) * 16;
    const int b_row = wn * 64 + (g >> 1) * 8 + r8;
    const int b_kb  = (g & 1) * 16;

    uint32_t a[2][4][4], b[2][4][4];

    int s = 0;
    for (int kt = 0; kt < KT; kt++) {
        if (kt + 1 < KT) cp_wait<1>(); else cp_wait<0>();
        __syncthreads();

        if (kt + 2 < KT) load_stage((kt + 2) % 3, kt + 2);

        const uint32_t abase = sb + s * T_ST_BYTES;
        const uint32_t bbase = sb + SMEM_B_OFF + s * T_ST_BYTES;

        #pragma unroll
        for (int mt = 0; mt < 4; mt++)
            ldsm_x4(abase + swz(((a_row + mt * 16) << 7) + a_kb), a[0][mt]);
        #pragma unroll
        for (int np = 0; np < 4; np++)
            ldsm_x4(bbase + swz(((b_row + np * 16) << 7) + b_kb), b[0][np]);

        #pragma unroll
        for (int ks = 0; ks < 4; ks++) {
            const int cur = ks & 1;
            if (ks < 3) {
                const int nxt = cur ^ 1;
                #pragma unroll
                for (int mt = 0; mt < 4; mt++)
                    ldsm_x4(abase + swz(((a_row + mt * 16) << 7) + (ks + 1) * 32 + a_kb), a[nxt][mt]);
                #pragma unroll
                for (int np = 0; np < 4; np++)
                    ldsm_x4(bbase + swz(((b_row + np * 16) << 7) + (ks + 1) * 32 + b_kb), b[nxt][np]);
            }
            #pragma unroll
            for (int mt = 0; mt < 4; mt++)
                #pragma unroll
                for (int np = 0; np < 4; np++) {
                    mma_bf16(acc[mt][np * 2],     a[cur][mt], &b[cur][np][0]);
                    mma_bf16(acc[mt][np * 2 + 1], a[cur][mt], &b[cur][np][2]);
                }
        }
        s++; if (s == 3) s = 0;
    }

    const int lr = lane >> 2, lc = (lane & 3) * 2;

    #pragma unroll
    for (int mt = 0; mt < 4; mt++) {
        #pragma unroll
        for (int h = 0; h < 2; h++) {
            const int row = bm + wm * 64 + mt * 16 + h * 8 + lr;
            #pragma unroll
            for (int nt = 0; nt < 8; nt++) {
                const int col = bn + wn * 64 + nt * 8 + lc;
                float v0 = __expf((acc[mt][nt][h * 2]     + vvec[col])     * INV_SCALE);
                float v1 = __expf((acc[mt][nt][h * 2 + 1] + vvec[col + 1]) * INV_SCALE);
                uint32_t* dst = (uint32_t*)(att + (size_t)row * NTOK + col);
                *dst = pack_bf16(v0, v1);
            }
        }
    }
}

// ---------------------------------------------------------------------------
// Split-K final GEMM: part[z] = att[:, z*KCHUNK:(z+1)*KCHUNK] @ PTchunk^T
// grid (8, 64, KSPLIT), 128 threads, same proven mainloop. Raw fp32 out.
// ---------------------------------------------------------------------------
__global__ __launch_bounds__(128, 2)
void gemm_fsplit(const __nv_bfloat16* __restrict__ A,   // att [NTOK, NTOK]
                 const __nv_bfloat16* __restrict__ B,   // PT  [DIM, NTOK]
                 float* __restrict__ part)
{
    extern __shared__ char smem[];
    const uint32_t sb = smem_u32(smem);
    const int tid = threadIdx.x, lane = tid & 31, wid = tid >> 5;
    const int wn = wid & 1, wm = wid >> 1;
    const int bm = blockIdx.y * BM, bn = blockIdx.x * BN;
    const int kbase = blockIdx.z * KCHUNK;
    const int KT = KCHUNK / BK;                  // 32

    float acc[4][8][4];
    #pragma unroll
    for (int i = 0; i < 4; i++)
        #pragma unroll
        for (int j = 0; j < 8; j++)
            #pragma unroll
            for (int q = 0; q < 4; q++) acc[i][j][q] = 0.0f;

    auto load_stage = [&](int s, int kt) {
        const int k0 = kbase + kt * BK;
        const uint32_t ab = sb + s * T_ST_BYTES;
        const __nv_bfloat16* Ag = A + (size_t)bm * NTOK + k0;
        #pragma unroll
        for (int i = 0; i < 8; i++) {
            int c = tid + (i << 7);
            int r = c >> 3, kc = c & 7;
            cp16(ab + swz((r << 7) + (kc << 4)), Ag + (size_t)r * NTOK + (kc << 3));
        }
        const uint32_t bb = sb + SMEM_B_OFF + s * T_ST_BYTES;
        const __nv_bfloat16* Bg = B + (size_t)bn * NTOK + k0;
        #pragma unroll
        for (int i = 0; i < 8; i++) {
            int c = tid + (i << 7);
            int r = c >> 3, kc = c & 7;
            cp16(bb + swz((r << 7) + (kc << 4)), Bg + (size_t)r * NTOK + (kc << 3));
        }
        cp_commit();
    };

    load_stage(0, 0);
    load_stage(1, 1);

    const int g = lane >> 3, r8 = lane & 7;
    const int a_row = wm * 64 + (g & 1) * 8 + r8;
    const int a_kb  = (g >> 1) * 16;
    const int b_row = wn * 64 + (g >> 1) * 8 + r8;
    const int b_kb  = (g & 1) * 16;

    uint32_t a[2][4][4], b[2][4][4];

    int s = 0;
    for (int kt = 0; kt < KT; kt++) {
        if (kt + 1 < KT) cp_wait<1>(); else cp_wait<0>();
        __syncthreads();

        if (kt + 2 < KT) load_stage((kt + 2) % 3, kt + 2);

        const uint32_t abase = sb + s * T_ST_BYTES;
        const uint32_t bbase = sb + SMEM_B_OFF + s * T_ST_BYTES;

        #pragma unroll
        for (int mt = 0; mt < 4; mt++)
            ldsm_x4(abase + swz(((a_row + mt * 16) << 7) + a_kb), a[0][mt]);
        #pragma unroll
        for (int np = 0; np < 4; np++)
            ldsm_x4(bbase + swz(((b_row + np * 16) << 7) + b_kb), b[0][np]);

        #pragma unroll
        for (int ks = 0; ks < 4; ks++) {
            const int cur = ks & 1;
            if (ks < 3) {
                const int nxt = cur ^ 1;
                #pragma unroll
                for (int mt = 0; mt < 4; mt++)
                    ldsm_x4(abase + swz(((a_row + mt * 16) << 7) + (ks + 1) * 32 + a_kb), a[nxt][mt]);
                #pragma unroll
                for (int np = 0; np < 4; np++)
                    ldsm_x4(bbase + swz(((b_row + np * 16) << 7) + (ks + 1) * 32 + b_kb), b[nxt][np]);
            }
            #pragma unroll
            for (int mt = 0; mt < 4; mt++)
                #pragma unroll
                for (int np = 0; np < 4; np++) {
                    mma_bf16(acc[mt][np * 2],     a[cur][mt], &b[cur][np][0]);
                    mma_bf16(acc[mt][np * 2 + 1], a[cur][mt], &b[cur][np][2]);
                }
        }
        s++; if (s == 3) s = 0;
    }

    const int lr = lane >> 2, lc = (lane & 3) * 2;
    float* base = part + (size_t)blockIdx.z * NTOK * DIM;

    #pragma unroll
    for (int mt = 0; mt < 4; mt++) {
        #pragma unroll
        for (int h = 0; h < 2; h++) {
            const int row = bm + wm * 64 + mt * 16 + h * 8 + lr;
            #pragma unroll
            for (int nt = 0; nt < 8; nt++) {
                const int col = bn + wn * 64 + nt * 8 + lc;
                float2* dst = (float2*)(base + (size_t)row * DIM + col);
                *dst = make_float2(acc[mt][nt][h * 2], acc[mt][nt][h * 2 + 1]);
            }
        }
    }
}

// ---------------------------------------------------------------------------
// Reduce: out = ((p0+p1)+(p2+p3)) * (1/rs[row]) + bo + x  (deterministic)
// One block per row, 256 threads x 4 cols.
// ---------------------------------------------------------------------------
__global__ __launch_bounds__(256)
void reduce_final(const float* __restrict__ part, const float* __restrict__ rs,
                  const float* __restrict__ bo, const float* __restrict__ x,
                  float* __restrict__ out)
{
    const int row = blockIdx.x;
    const int c = threadIdx.x * 4;
    const float rcp = 1.0f / rs[row];
    const size_t off = (size_t)row * DIM + c;
    const size_t S = (size_t)NTOK * DIM;

    float4 p0 = *(const float4*)(part + off);
    float4 p1 = *(const float4*)(part + S + off);
    float4 p2 = *(const float4*)(part + 2 * S + off);
    float4 p3 = *(const float4*)(part + 3 * S + off);
    float4 xr = *(const float4*)(x + off);
    float4 bv = *(const float4*)(bo + c);

    float4 o;
    o.x = ((p0.x + p1.x) + (p2.x + p3.x)) * rcp + bv.x + xr.x;
    o.y = ((p0.y + p1.y) + (p2.y + p3.y)) * rcp + bv.y + xr.y;
    o.z = ((p0.z + p1.z) + (p2.z + p3.z)) * rcp + bv.z + xr.z;
    o.w = ((p0.w + p1.w) + (p2.w + p3.w)) * rcp + bv.w + xr.w;
    *(float4*)(out + off) = o;
}

// ---------------------------------------------------------------------------
// small vectors: y=0: wv[e] = sum_a Wk[a,e]*bq[a]; y=1: bv2[d] = Wo[d,:].bv
// ---------------------------------------------------------------------------
__global__ __launch_bounds__(128)
void smallvec(const float* __restrict__ Wk, const float* __restrict__ bq,
              const float* __restrict__ Wo, const float* __restrict__ bv,
              float* __restrict__ wv, float* __restrict__ bv2)
{
    const int i = blockIdx.x * 128 + threadIdx.x;
    if (blockIdx.y == 0) {
        float s = 0.0f;
        for (int a = 0; a < DIM; a++) s += Wk[(size_t)a * DIM + i] * bq[a];
        wv[i] = s;
    } else {
        float s = 0.0f;
        for (int e = 0; e < DIM; e++) s += Wo[(size_t)i * DIM + e] * bv[e];
        bv2[i] = s;
    }
}

// v[i] = x[i,:] . wv   (warp per row, deterministic)
__global__ __launch_bounds__(256)
void gemv_v(const float* __restrict__ x, const float* __restrict__ wv,
            float* __restrict__ v)
{
    const int lane = threadIdx.x & 31, warp = threadIdx.x >> 5;
    const int row = blockIdx.x * 8 + warp;
    const float* p = x + (size_t)row * DIM;
    float s = 0.0f;
    #pragma unroll
    for (int k = 0; k < 32; k++) s += p[lane + k * 32] * wv[lane + k * 32];
    #pragma unroll
    for (int o = 16; o > 0; o >>= 1) s += __shfl_xor_sync(0xFFFFFFFF, s, o);
    if (lane == 0) v[row] = s;
}

// converts: y=0: x -> xb (bf16), y=1: Wo -> wob
__global__ __launch_bounds__(256)
void conv2(const float* __restrict__ x, const float* __restrict__ Wo,
           __nv_bfloat16* __restrict__ xo, __nv_bfloat16* __restrict__ oo)
{
    const float* in; __nv_bfloat16* out; int n4;
    if (blockIdx.y == 0) { in = x;  out = xo; n4 = NTOK * DIM / 4; }
    else                 { in = Wo; out = oo; n4 = DIM * DIM / 4; }
    int i = blockIdx.x * blockDim.x + threadIdx.x;
    if (i >= n4) return;
    float4 v = reinterpret_cast<const float4*>(in)[i];
    uint2 o;
    o.x = pack_bf16(v.x, v.y);
    o.y = pack_bf16(v.z, v.w);
    reinterpret_cast<uint2*>(out)[i] = o;
}

// transpose-convert: out[d,f] = bf16(W[f,d]), 1024x1024, z picks Wq/Wk/Wv
__global__ __launch_bounds__(256)
void tconv(const float* __restrict__ Wq, const float* __restrict__ Wk,
           const float* __restrict__ Wv,
           __nv_bfloat16* __restrict__ oq, __nv_bfloat16* __restrict__ ok,
           __nv_bfloat16* __restrict__ ov)
{
    __shared__ float t[32][33];
    const float* in; __nv_bfloat16* out;
    if (blockIdx.z == 0)      { in = Wq; out = oq; }
    else if (blockIdx.z == 1) { in = Wk; out = ok; }
    else                      { in = Wv; out = ov; }
    const int bx = blockIdx.x * 32;
    const int by = blockIdx.y * 32;
    const int x = threadIdx.x, y = threadIdx.y;
    #pragma unroll
    for (int i = 0; i < 32; i += 8)
        t[y + i][x] = in[(size_t)(by + y + i) * DIM + bx + x];
    __syncthreads();
    #pragma unroll
    for (int i = 0; i < 32; i += 8)
        out[(size_t)(bx + y + i) * DIM + by + x] = __float2bfloat16(t[x][y + i]);
}

// ---------------------------------------------------------------------------
// Row sums of att (bf16, unnormalized exp) -> fp32. Deterministic tree.
// ---------------------------------------------------------------------------
__global__ __launch_bounds__(256)
void rowsum_kernel(const __nv_bfloat16* __restrict__ att, float* __restrict__ rs)
{
    const int row = blockIdx.x;
    const uint4* p = reinterpret_cast<const uint4*>(att + (size_t)row * NTOK);
    const int tid = threadIdx.x, lane = tid & 31, warp = tid >> 5;
    __shared__ float red[8];

    float s = 0.0f;
    #pragma unroll
    for (int i = 0; i < 4; i++) {
        uint4 u = p[tid + i * 256];
        float2 f0 = __bfloat1622float2(*reinterpret_cast<__nv_bfloat162*>(&u.x));
        float2 f1 = __bfloat1622float2(*reinterpret_cast<__nv_bfloat162*>(&u.y));
        float2 f2 = __bfloat1622float2(*reinterpret_cast<__nv_bfloat162*>(&u.z));
        float2 f3 = __bfloat1622float2(*reinterpret_cast<__nv_bfloat162*>(&u.w));
        s += ((f0.x + f0.y) + (f1.x + f1.y)) + ((f2.x + f2.y) + (f3.x + f3.y));
    }
    #pragma unroll
    for (int o = 16; o > 0; o >>= 1) s += __shfl_xor_sync(0xFFFFFFFF, s, o);
    if (lane == 0) red[warp] = s;
    __syncthreads();
    if (warp == 0) {
        s = red[lane & 7];
        #pragma unroll
        for (int o = 4; o > 0; o >>= 1) s += __shfl_xor_sync(0xFFFFFFFF, s, o);
        if (lane == 0) rs[row] = s;
    }
}

// ---------------------------------------------------------------------------
// Launch
// ---------------------------------------------------------------------------
extern "C" void kernel_launch(void* const* d_in, const int* in_sizes, int n_in,
                              void* d_out, int out_size)
{
    const float* x  = (const float*)d_in[0];
    const float* Wq = (const float*)d_in[1];
    const float* bq = (const float*)d_in[2];
    const float* Wk = (const float*)d_in[3];
    const float* bk = (const float*)d_in[4];
    const float* Wv = (const float*)d_in[5];
    const float* bv = (const float*)d_in[6];
    const float* Wo = (const float*)d_in[7];
    const float* bo = (const float*)d_in[8];
    float* out = (float*)d_out;
    (void)bk;  // cancels in softmax (row-constant)

    __nv_bfloat16 *xb, *wob, *wqT, *wkT, *wvT, *y, *PT, *att;
    float *rs, *wv, *bv2, *vv, *part;
    cudaGetSymbolAddress((void**)&xb,   g_xb);
    cudaGetSymbolAddress((void**)&wob,  g_wob);
    cudaGetSymbolAddress((void**)&wqT,  g_wqT);
    cudaGetSymbolAddress((void**)&wkT,  g_wkT);
    cudaGetSymbolAddress((void**)&wvT,  g_wvT);
    cudaGetSymbolAddress((void**)&y,    g_y);
    cudaGetSymbolAddress((void**)&PT,   g_PT);
    cudaGetSymbolAddress((void**)&att,  g_att);
    cudaGetSymbolAddress((void**)&rs,   g_rs);
    cudaGetSymbolAddress((void**)&wv,   g_wv);
    cudaGetSymbolAddress((void**)&bv2,  g_bv2);
    cudaGetSymbolAddress((void**)&vv,   g_v);
    cudaGetSymbolAddress((void**)&part, g_part);

    cudaFuncSetAttribute(gemm_smallmm, cudaFuncAttributeMaxDynamicSharedMemorySize, SMEM_TOTAL);
    cudaFuncSetAttribute(gemm_projs,   cudaFuncAttributeMaxDynamicSharedMemorySize, SMEM_TOTAL);
    cudaFuncSetAttribute(gemm_z,       cudaFuncAttributeMaxDynamicSharedMemorySize, SMEM_TOTAL);
    cudaFuncSetAttribute(gemm_fsplit,  cudaFuncAttributeMaxDynamicSharedMemorySize, SMEM_TOTAL);

    // 1: small vectors wv, bv2
    smallvec<<<dim3(8, 2), 128>>>(Wk, bq, Wo, bv, wv, bv2);

    // 2: converts x->xb, Wo->wob
    {
        int gx = (NTOK * DIM / 4 + 255) / 256;
        conv2<<<dim3(gx, 2), 256>>>(x, Wo, xb, wob);
    }

    // 3: transpose-converts Wq^T, Wk^T, Wv^T
    tconv<<<dim3(32, 32, 3), dim3(32, 8)>>>(Wq, Wk, Wv, wqT, wkT, wvT);

    // 4: v = x . wv
    gemv_v<<<NTOK / 8, 256>>>(x, wv, vv);

    // 5: Mt = NT(WkT, WqT), W2 = NT(Wo, WvT)
    gemm_smallmm<<<dim3(8, 8, 2), 256, SMEM_TOTAL>>>();

    // 6: y = NT(xb, Mt);  PT = NT(W2, xb) + bv2[row]
    gemm_projs<<<dim3(64, 8, 2), 256, SMEM_TOTAL>>>();

    // 7: att = exp((y @ xb^T + v_j) * inv_scale)
    gemm_z<<<dim3(64, 64), 128, SMEM_TOTAL>>>(y, xb, vv, att);

    // 8: rs[row] = sum of att row
    rowsum_kernel<<<NTOK, 256>>>(att, rs);

    // 9: split-K partials of att @ PT^T
    gemm_fsplit<<<dim3(8, 64, KSPLIT), 128, SMEM_TOTAL>>>(att, PT, part);

    // 10: out = sum(partials)/rs + bo + x
    reduce_final<<<NTOK, 256>>>(part, rs, bo, x, out);
}